// round 1
// baseline (speedup 1.0000x reference)
#include <cuda_runtime.h>
#include <cuda_bf16.h>
#include <math.h>

// Problem constants
#define BATCH   32
#define GRID    64          // NH == NW
#define DIM     384
#define HEADS   12
#define HD      32
#define INNER   (HEADS*HD)  // 384
#define WS      8
#define M2      64          // WS*WS
#define NWIN    64          // (64/8)*(64/8)
#define DISP    4
#define CPB_H   512

#define ROWS    (BATCH*GRID*GRID)      // 131072
#define QKV_N   (3*INNER)              // 1152

// ---- device scratch (no runtime allocation allowed) ----
// q,k,v in attention layout: [b][h][w][i][d]
__device__ float g_q [ (size_t)BATCH*HEADS*NWIN*M2*HD ];
__device__ float g_k [ (size_t)BATCH*HEADS*NWIN*M2*HD ];
__device__ float g_v [ (size_t)BATCH*HEADS*NWIN*M2*HD ];
// attention output merged back to [b][H][W][inner] (shifted coords)
__device__ float g_ao[ (size_t)BATCH*GRID*GRID*INNER ];
// CPB bias table [h][i][j]
__device__ float g_bias[ HEADS*M2*M2 ];

// ============================================================
// CPB MLP: bias[h][i][j] = relu(rel(i,j) @ w1^T + b1) @ w2^T + b2
// ============================================================
__global__ __launch_bounds__(256) void cpb_kernel(
    const float* __restrict__ w1, const float* __restrict__ b1,
    const float* __restrict__ w2, const float* __restrict__ b2)
{
    __shared__ float sw2[HEADS*CPB_H];   // 24KB
    __shared__ float sw1[CPB_H*2];
    __shared__ float sb1[CPB_H];
    int tid = threadIdx.x;
    for (int t = tid; t < HEADS*CPB_H; t += 256) sw2[t] = w2[t];
    for (int t = tid; t < CPB_H*2;     t += 256) sw1[t] = w1[t];
    for (int t = tid; t < CPB_H;       t += 256) sb1[t] = b1[t];
    __syncthreads();

    int e = blockIdx.x*256 + tid;       // 0..4095 -> (i,j)
    int i = e >> 6, j = e & 63;
    float dx = (float)(j>>3) - (float)(i>>3);
    float dy = (float)(j&7)  - (float)(i&7);
    float r0 = (dx >= 0.f) ? log1pf(dx) : -log1pf(-dx);
    float r1 = (dy >= 0.f) ? log1pf(dy) : -log1pf(-dy);

    float acc[HEADS];
    #pragma unroll
    for (int h = 0; h < HEADS; h++) acc[h] = 0.f;

    for (int c = 0; c < CPB_H; c++) {
        float hid = fmaf(r0, sw1[2*c], fmaf(r1, sw1[2*c+1], sb1[c]));
        hid = fmaxf(hid, 0.f);
        #pragma unroll
        for (int h = 0; h < HEADS; h++)
            acc[h] = fmaf(hid, sw2[h*CPB_H + c], acc[h]);
    }
    #pragma unroll
    for (int h = 0; h < HEADS; h++)
        g_bias[h*M2*M2 + e] = acc[h] + b2[h];
}

// ============================================================
// QKV GEMM: [131072 x 384] @ [384 x 1152], roll(-4,-4) folded into A reads,
// window partition folded into the scattered store into g_q/g_k/g_v.
// 128x128x8 tile, 256 threads, 8x8 microtile.
// ============================================================
__global__ __launch_bounds__(256) void qkv_gemm(
    const float* __restrict__ x, const float* __restrict__ wqkv)
{
    __shared__ __align__(16) float As[8][128];
    __shared__ __align__(16) float Bs[8][128];

    int tid = threadIdx.x;
    int m0 = blockIdx.y * 128;
    int n0 = blockIdx.x * 128;

    int lm = tid >> 1;              // 0..127
    int lk = (tid & 1) * 4;         // 0 or 4

    // A row with cyclic shift (-DISP,-DISP)
    int r  = m0 + lm;
    int bb = r >> 12;
    int H  = (r >> 6) & 63;
    int W  = r & 63;
    const float* arow = x + (((size_t)bb*GRID + ((H+DISP)&63))*GRID + ((W+DISP)&63))*(size_t)DIM;
    const float* brow = wqkv + (size_t)(n0 + lm)*DIM;

    int tx = tid & 15, ty = tid >> 4;

    float acc[8][8];
    #pragma unroll
    for (int i = 0; i < 8; i++)
        #pragma unroll
        for (int j = 0; j < 8; j++) acc[i][j] = 0.f;

    for (int k0 = 0; k0 < DIM; k0 += 8) {
        float4 av = *(const float4*)(arow + k0 + lk);
        float4 bv = *(const float4*)(brow + k0 + lk);
        As[lk+0][lm]=av.x; As[lk+1][lm]=av.y; As[lk+2][lm]=av.z; As[lk+3][lm]=av.w;
        Bs[lk+0][lm]=bv.x; Bs[lk+1][lm]=bv.y; Bs[lk+2][lm]=bv.z; Bs[lk+3][lm]=bv.w;
        __syncthreads();
        #pragma unroll
        for (int kk = 0; kk < 8; kk++) {
            float4 a0 = *(const float4*)&As[kk][ty*8];
            float4 a1 = *(const float4*)&As[kk][ty*8+4];
            float4 b0 = *(const float4*)&Bs[kk][tx*8];
            float4 b1 = *(const float4*)&Bs[kk][tx*8+4];
            float av8[8] = {a0.x,a0.y,a0.z,a0.w,a1.x,a1.y,a1.z,a1.w};
            float bv8[8] = {b0.x,b0.y,b0.z,b0.w,b1.x,b1.y,b1.z,b1.w};
            #pragma unroll
            for (int i = 0; i < 8; i++)
                #pragma unroll
                for (int j = 0; j < 8; j++)
                    acc[i][j] = fmaf(av8[i], bv8[j], acc[i][j]);
        }
        __syncthreads();
    }

    // scatter store to q/k/v in window layout
    int nn    = n0 + tx*8;
    int which = nn / INNER;
    int hh_   = (nn % INNER) >> 5;
    int d0    = nn & 31;
    float* gp = (which == 0) ? g_q : (which == 1) ? g_k : g_v;

    #pragma unroll
    for (int i = 0; i < 8; i++) {
        int rr = m0 + ty*8 + i;
        int b2_ = rr >> 12;
        int Hh  = (rr >> 6) & 63;
        int Ww  = rr & 63;
        int w   = (Hh >> 3) * 8 + (Ww >> 3);
        int ii  = (Hh & 7) * 8 + (Ww & 7);
        size_t base = ((((size_t)b2_*HEADS + hh_)*NWIN + w)*M2 + ii)*HD + d0;
        float4 v0 = make_float4(acc[i][0],acc[i][1],acc[i][2],acc[i][3]);
        float4 v1 = make_float4(acc[i][4],acc[i][5],acc[i][6],acc[i][7]);
        *(float4*)(gp + base)     = v0;
        *(float4*)(gp + base + 4) = v1;
    }
}

// ============================================================
// Fused per-window attention: one block per (b,h,w).
// normalize q,k; dots = q@k^T / max(tau,.01) + bias + masks; softmax;
// write attn (optional); out = attn @ v -> g_ao in merged layout.
// ============================================================
__global__ __launch_bounds__(256) void attn_kernel(
    const float* __restrict__ tau, float* __restrict__ attn_out)
{
    __shared__ __align__(16) float sq[M2][HD];
    __shared__ __align__(16) float sk[M2][HD];
    __shared__ __align__(16) float sv[M2][HD];
    __shared__ __align__(16) float sd[M2][M2];

    int blk = blockIdx.x;               // ((b*HEADS + h)*NWIN + w)
    int w   = blk & 63;
    int bh  = blk >> 6;
    int h   = bh % HEADS;
    int tid = threadIdx.x;

    size_t base = (size_t)blk * (M2*HD);
    #pragma unroll
    for (int u = 0; u < 2; u++) {
        int idx = tid*8 + u*4;
        *(float4*)(&sq[0][0] + idx) = *(const float4*)(g_q + base + idx);
        *(float4*)(&sk[0][0] + idx) = *(const float4*)(g_k + base + idx);
        *(float4*)(&sv[0][0] + idx) = *(const float4*)(g_v + base + idx);
    }
    __syncthreads();

    // L2 normalize rows of q (threads 0..63) and k (64..127)
    if (tid < 128) {
        float* row = (tid < 64) ? sq[tid] : sk[tid-64];
        float s = 0.f;
        #pragma unroll
        for (int d = 0; d < HD; d++) s = fmaf(row[d], row[d], s);
        float inv = 1.f / fmaxf(sqrtf(s), 1e-12f);
        #pragma unroll
        for (int d = 0; d < HD; d++) row[d] *= inv;
    }
    __syncthreads();

    float inv_tau = 1.f / fmaxf(tau[h], 0.01f);
    int wh = w >> 3, ww = w & 7;
    bool mUL = (wh == 7), mLR = (ww == 7);

    // dots: each thread handles one row i, 16 columns
    {
        int i  = tid >> 2;
        int j0 = (tid & 3) * 16;
        float qreg[HD];
        #pragma unroll
        for (int d = 0; d < HD; d++) qreg[d] = sq[i][d];
        const float* biasrow = g_bias + ((size_t)h*M2 + i)*M2;
        bool iu = (i >= 32);
        bool il = ((i & 7) >= 4);
        #pragma unroll 4
        for (int u = 0; u < 16; u++) {
            int j = j0 + u;
            const float4* kr = (const float4*)sk[j];
            float s = 0.f;
            #pragma unroll
            for (int d4 = 0; d4 < 8; d4++) {
                float4 kv = kr[d4];
                s = fmaf(qreg[d4*4+0], kv.x, s);
                s = fmaf(qreg[d4*4+1], kv.y, s);
                s = fmaf(qreg[d4*4+2], kv.z, s);
                s = fmaf(qreg[d4*4+3], kv.w, s);
            }
            float val = fmaf(s, inv_tau, biasrow[j]);
            if (mUL && (iu != (j >= 32)))        val = -1e30f;
            if (mLR && (il != ((j & 7) >= 4)))   val = -1e30f;
            sd[i][j] = val;
        }
    }
    __syncthreads();

    // softmax: 8 warps x 8 rows each; 2 cols per lane
    {
        int lane = tid & 31, wp = tid >> 5;
        for (int rr = 0; rr < 8; rr++) {
            int row = wp*8 + rr;
            float v0 = sd[row][lane], v1 = sd[row][lane+32];
            float mx = fmaxf(v0, v1);
            #pragma unroll
            for (int o = 16; o > 0; o >>= 1)
                mx = fmaxf(mx, __shfl_xor_sync(0xffffffffu, mx, o));
            float e0 = __expf(v0 - mx), e1 = __expf(v1 - mx);
            float sm = e0 + e1;
            #pragma unroll
            for (int o = 16; o > 0; o >>= 1)
                sm += __shfl_xor_sync(0xffffffffu, sm, o);
            float inv = 1.f / sm;
            e0 *= inv; e1 *= inv;
            sd[row][lane]    = e0;
            sd[row][lane+32] = e1;
            if (attn_out) {
                size_t ab = ((size_t)blk*M2 + row)*M2;
                attn_out[ab + lane]      = e0;
                attn_out[ab + lane + 32] = e1;
            }
        }
    }
    __syncthreads();

    // out = attn @ v ; write merged layout
    {
        int i  = tid >> 2;
        int d0 = (tid & 3) * 8;
        float acc[8];
        #pragma unroll
        for (int u = 0; u < 8; u++) acc[u] = 0.f;
        #pragma unroll 8
        for (int j = 0; j < 64; j++) {
            float a  = sd[i][j];
            float4 v0 = *(const float4*)&sv[j][d0];
            float4 v1 = *(const float4*)&sv[j][d0+4];
            acc[0] = fmaf(a, v0.x, acc[0]);
            acc[1] = fmaf(a, v0.y, acc[1]);
            acc[2] = fmaf(a, v0.z, acc[2]);
            acc[3] = fmaf(a, v0.w, acc[3]);
            acc[4] = fmaf(a, v1.x, acc[4]);
            acc[5] = fmaf(a, v1.y, acc[5]);
            acc[6] = fmaf(a, v1.z, acc[6]);
            acc[7] = fmaf(a, v1.w, acc[7]);
        }
        int b  = bh / HEADS;
        int Hh = wh*8 + (i >> 3);
        int Ww = ww*8 + (i & 7);
        float* op = g_ao + (((size_t)b*GRID + Hh)*GRID + Ww)*INNER + h*HD + d0;
        *(float4*)op     = make_float4(acc[0],acc[1],acc[2],acc[3]);
        *(float4*)(op+4) = make_float4(acc[4],acc[5],acc[6],acc[7]);
    }
}

// ============================================================
// Output projection: y = ao @ w_out^T + b_out, roll(+4,+4) folded into
// the A-row mapping (output row r reads ao at shifted coords).
// ============================================================
__global__ __launch_bounds__(256) void out_gemm(
    const float* __restrict__ wout, const float* __restrict__ bout,
    float* __restrict__ y)
{
    __shared__ __align__(16) float As[8][128];
    __shared__ __align__(16) float Bs[8][128];

    int tid = threadIdx.x;
    int m0 = blockIdx.y * 128;
    int n0 = blockIdx.x * 128;

    int lm = tid >> 1;
    int lk = (tid & 1) * 4;

    int r  = m0 + lm;                 // OUTPUT row
    int bb = r >> 12;
    int H  = (r >> 6) & 63;
    int W  = r & 63;
    const float* arow = g_ao + (((size_t)bb*GRID + ((H+60)&63))*GRID + ((W+60)&63))*(size_t)INNER;
    const float* brow = wout + (size_t)(n0 + lm)*INNER;

    int tx = tid & 15, ty = tid >> 4;

    float acc[8][8];
    #pragma unroll
    for (int i = 0; i < 8; i++)
        #pragma unroll
        for (int j = 0; j < 8; j++) acc[i][j] = 0.f;

    for (int k0 = 0; k0 < INNER; k0 += 8) {
        float4 av = *(const float4*)(arow + k0 + lk);
        float4 bv = *(const float4*)(brow + k0 + lk);
        As[lk+0][lm]=av.x; As[lk+1][lm]=av.y; As[lk+2][lm]=av.z; As[lk+3][lm]=av.w;
        Bs[lk+0][lm]=bv.x; Bs[lk+1][lm]=bv.y; Bs[lk+2][lm]=bv.z; Bs[lk+3][lm]=bv.w;
        __syncthreads();
        #pragma unroll
        for (int kk = 0; kk < 8; kk++) {
            float4 a0 = *(const float4*)&As[kk][ty*8];
            float4 a1 = *(const float4*)&As[kk][ty*8+4];
            float4 b0 = *(const float4*)&Bs[kk][tx*8];
            float4 b1 = *(const float4*)&Bs[kk][tx*8+4];
            float av8[8] = {a0.x,a0.y,a0.z,a0.w,a1.x,a1.y,a1.z,a1.w};
            float bv8[8] = {b0.x,b0.y,b0.z,b0.w,b1.x,b1.y,b1.z,b1.w};
            #pragma unroll
            for (int i = 0; i < 8; i++)
                #pragma unroll
                for (int j = 0; j < 8; j++)
                    acc[i][j] = fmaf(av8[i], bv8[j], acc[i][j]);
        }
        __syncthreads();
    }

    int nn = n0 + tx*8;
    float bo[8];
    #pragma unroll
    for (int j = 0; j < 8; j++) bo[j] = bout[nn + j];

    #pragma unroll
    for (int i = 0; i < 8; i++) {
        size_t rr = (size_t)(m0 + ty*8 + i);
        float4 v0 = make_float4(acc[i][0]+bo[0],acc[i][1]+bo[1],acc[i][2]+bo[2],acc[i][3]+bo[3]);
        float4 v1 = make_float4(acc[i][4]+bo[4],acc[i][5]+bo[5],acc[i][6]+bo[6],acc[i][7]+bo[7]);
        *(float4*)(y + rr*DIM + nn)     = v0;
        *(float4*)(y + rr*DIM + nn + 4) = v1;
    }
}

// ============================================================
extern "C" void kernel_launch(void* const* d_in, const int* in_sizes, int n_in,
                              void* d_out, int out_size)
{
    const float* x    = (const float*)d_in[0];
    const float* wqkv = (const float*)d_in[1];
    const float* w1   = (const float*)d_in[2];
    const float* b1   = (const float*)d_in[3];
    const float* w2   = (const float*)d_in[4];
    const float* b2   = (const float*)d_in[5];
    const float* tau  = (const float*)d_in[6];
    const float* wout = (const float*)d_in[7];
    const float* bout = (const float*)d_in[8];

    float* out = (float*)d_out;
    const long long OUT_E  = (long long)ROWS * DIM;                    // 50331648
    const long long ATTN_E = (long long)BATCH*HEADS*NWIN*M2*M2;       // 100663296
    float* attn = ((long long)out_size >= OUT_E + ATTN_E) ? (out + OUT_E) : nullptr;

    cpb_kernel<<<16, 256>>>(w1, b1, w2, b2);
    qkv_gemm<<<dim3(QKV_N/128, ROWS/128), 256>>>(x, wqkv);
    attn_kernel<<<BATCH*HEADS*NWIN, 256>>>(tau, attn);
    out_gemm<<<dim3(DIM/128, ROWS/128), 256>>>(wout, bout, out);
}

// round 2
// speedup vs baseline: 2.1352x; 2.1352x over previous
#include <cuda_runtime.h>
#include <cuda_bf16.h>
#include <math.h>

// Problem constants
#define BATCH   32
#define GRID    64
#define DIM     384
#define HEADS   12
#define HD      32
#define INNER   (HEADS*HD)  // 384
#define WS      8
#define M2      64
#define NWIN    64
#define DISP    4
#define CPB_H   512

#define ROWS    (BATCH*GRID*GRID)      // 131072
#define QKV_N   (3*INNER)              // 1152

// ---- device scratch ----
__device__ float g_q [ (size_t)BATCH*HEADS*NWIN*M2*HD ];
__device__ float g_k [ (size_t)BATCH*HEADS*NWIN*M2*HD ];
__device__ float g_v [ (size_t)BATCH*HEADS*NWIN*M2*HD ];
__device__ float g_ao[ (size_t)BATCH*GRID*GRID*INNER ];
__device__ float g_bias[ HEADS*M2*M2 ];

// ============================================================
// CPB MLP (unchanged)
// ============================================================
__global__ __launch_bounds__(256) void cpb_kernel(
    const float* __restrict__ w1, const float* __restrict__ b1,
    const float* __restrict__ w2, const float* __restrict__ b2)
{
    __shared__ float sw2[HEADS*CPB_H];
    __shared__ float sw1[CPB_H*2];
    __shared__ float sb1[CPB_H];
    int tid = threadIdx.x;
    for (int t = tid; t < HEADS*CPB_H; t += 256) sw2[t] = w2[t];
    for (int t = tid; t < CPB_H*2;     t += 256) sw1[t] = w1[t];
    for (int t = tid; t < CPB_H;       t += 256) sb1[t] = b1[t];
    __syncthreads();

    int e = blockIdx.x*256 + tid;
    int i = e >> 6, j = e & 63;
    float dx = (float)(j>>3) - (float)(i>>3);
    float dy = (float)(j&7)  - (float)(i&7);
    float r0 = (dx >= 0.f) ? log1pf(dx) : -log1pf(-dx);
    float r1 = (dy >= 0.f) ? log1pf(dy) : -log1pf(-dy);

    float acc[HEADS];
    #pragma unroll
    for (int h = 0; h < HEADS; h++) acc[h] = 0.f;

    for (int c = 0; c < CPB_H; c++) {
        float hid = fmaf(r0, sw1[2*c], fmaf(r1, sw1[2*c+1], sb1[c]));
        hid = fmaxf(hid, 0.f);
        #pragma unroll
        for (int h = 0; h < HEADS; h++)
            acc[h] = fmaf(hid, sw2[h*CPB_H + c], acc[h]);
    }
    #pragma unroll
    for (int h = 0; h < HEADS; h++)
        g_bias[h*M2*M2 + e] = acc[h] + b2[h];
}

// ============================================================
// bf16x3 tensor-core GEMM machinery
// ============================================================
__device__ __forceinline__ void mma16816(float d[4], const unsigned a[4], const unsigned b[2]) {
    asm volatile(
        "mma.sync.aligned.m16n8k16.row.col.f32.bf16.bf16.f32 "
        "{%0,%1,%2,%3}, {%4,%5,%6,%7}, {%8,%9}, {%0,%1,%2,%3};\n"
        : "+f"(d[0]), "+f"(d[1]), "+f"(d[2]), "+f"(d[3])
        : "r"(a[0]), "r"(a[1]), "r"(a[2]), "r"(a[3]), "r"(b[0]), "r"(b[1]));
}

// 16 floats -> hi: 2x uint4 (8 bf16 pairs), lo: 2x uint4
__device__ __forceinline__ void cvt16(const float* f, uint4* hi, uint4* lo) {
    #pragma unroll
    for (int c = 0; c < 2; c++) {
        unsigned h[4], l[4];
        #pragma unroll
        for (int i = 0; i < 4; i++) {
            float f0 = f[c*8 + 2*i], f1 = f[c*8 + 2*i + 1];
            __nv_bfloat16 h0 = __float2bfloat16(f0);
            __nv_bfloat16 h1 = __float2bfloat16(f1);
            float r0 = f0 - __bfloat162float(h0);
            float r1 = f1 - __bfloat162float(h1);
            __nv_bfloat16 l0 = __float2bfloat16(r0);
            __nv_bfloat16 l1 = __float2bfloat16(r1);
            h[i] = ((unsigned)__bfloat16_as_ushort(h1) << 16) | __bfloat16_as_ushort(h0);
            l[i] = ((unsigned)__bfloat16_as_ushort(l1) << 16) | __bfloat16_as_ushort(l0);
        }
        hi[c] = make_uint4(h[0], h[1], h[2], h[3]);
        lo[c] = make_uint4(l[0], l[1], l[2], l[3]);
    }
}

#define SMS 40   // smem row stride in bf16 (80B: conflict-free, 16B aligned)

// ============================================================
// QKV GEMM: bf16x3 mma. M=131072, N=1152, K=384. Tile 128x128x32.
// ============================================================
__global__ __launch_bounds__(256) void qkv_gemm(
    const float* __restrict__ x, const float* __restrict__ wqkv)
{
    __shared__ __align__(16) __nv_bfloat16 Ah[128][SMS];
    __shared__ __align__(16) __nv_bfloat16 Al[128][SMS];
    __shared__ __align__(16) __nv_bfloat16 Bh[128][SMS];
    __shared__ __align__(16) __nv_bfloat16 Bl[128][SMS];

    const int tid  = threadIdx.x;
    const int m0   = blockIdx.y * 128;
    const int n0   = blockIdx.x * 128;
    const int lane = tid & 31, warp = tid >> 5;
    const int wm = warp & 1, wn = warp >> 1;      // 2 x 4 warps, each 64x32
    const int g  = lane >> 2, tg = lane & 3;

    const int rA = tid >> 1;
    const int cb = (tid & 1) * 16;
    {
    }
    int r  = m0 + rA;
    int bb = r >> 12, H = (r >> 6) & 63, W = r & 63;
    const float* arow = x + (((size_t)bb*GRID + ((H+DISP)&63))*GRID + ((W+DISP)&63))*(size_t)DIM + cb;
    const float* brow = wqkv + (size_t)(n0 + rA)*DIM + cb;

    float fa[16], fb[16];
    uint4 pah[2], pal[2], pbh[2], pbl[2];

    // prefetch + convert tile 0
    #pragma unroll
    for (int u = 0; u < 4; u++) {
        float4 va = *(const float4*)(arow + u*4);
        float4 vb = *(const float4*)(brow + u*4);
        fa[u*4+0]=va.x; fa[u*4+1]=va.y; fa[u*4+2]=va.z; fa[u*4+3]=va.w;
        fb[u*4+0]=vb.x; fb[u*4+1]=vb.y; fb[u*4+2]=vb.z; fb[u*4+3]=vb.w;
    }
    cvt16(fa, pah, pal);
    cvt16(fb, pbh, pbl);

    float acc[4][4][4];
    #pragma unroll
    for (int i = 0; i < 4; i++)
        #pragma unroll
        for (int j = 0; j < 4; j++)
            #pragma unroll
            for (int u = 0; u < 4; u++) acc[i][j][u] = 0.f;

    const int NT = DIM / 32;  // 12
    for (int t = 0; t < NT; t++) {
        __syncthreads();
        *(uint4*)&Ah[rA][cb]   = pah[0];  *(uint4*)&Ah[rA][cb+8] = pah[1];
        *(uint4*)&Al[rA][cb]   = pal[0];  *(uint4*)&Al[rA][cb+8] = pal[1];
        *(uint4*)&Bh[rA][cb]   = pbh[0];  *(uint4*)&Bh[rA][cb+8] = pbh[1];
        *(uint4*)&Bl[rA][cb]   = pbl[0];  *(uint4*)&Bl[rA][cb+8] = pbl[1];
        __syncthreads();

        if (t + 1 < NT) {
            const float* an = arow + (t+1)*32;
            const float* bn = brow + (t+1)*32;
            #pragma unroll
            for (int u = 0; u < 4; u++) {
                float4 va = *(const float4*)(an + u*4);
                float4 vb = *(const float4*)(bn + u*4);
                fa[u*4+0]=va.x; fa[u*4+1]=va.y; fa[u*4+2]=va.z; fa[u*4+3]=va.w;
                fb[u*4+0]=vb.x; fb[u*4+1]=vb.y; fb[u*4+2]=vb.z; fb[u*4+3]=vb.w;
            }
        }

        #pragma unroll
        for (int ks = 0; ks < 2; ks++) {
            unsigned ah[4][4], al[4][4], bh2[4][2], bl2[4][2];
            const int c0 = ks*16 + 2*tg;
            #pragma unroll
            for (int mi = 0; mi < 4; mi++) {
                int r0 = wm*64 + mi*16 + g;
                ah[mi][0] = *(const unsigned*)&Ah[r0  ][c0];
                ah[mi][1] = *(const unsigned*)&Ah[r0+8][c0];
                ah[mi][2] = *(const unsigned*)&Ah[r0  ][c0+8];
                ah[mi][3] = *(const unsigned*)&Ah[r0+8][c0+8];
                al[mi][0] = *(const unsigned*)&Al[r0  ][c0];
                al[mi][1] = *(const unsigned*)&Al[r0+8][c0];
                al[mi][2] = *(const unsigned*)&Al[r0  ][c0+8];
                al[mi][3] = *(const unsigned*)&Al[r0+8][c0+8];
            }
            #pragma unroll
            for (int nj = 0; nj < 4; nj++) {
                int nr = wn*32 + nj*8 + g;
                bh2[nj][0] = *(const unsigned*)&Bh[nr][c0];
                bh2[nj][1] = *(const unsigned*)&Bh[nr][c0+8];
                bl2[nj][0] = *(const unsigned*)&Bl[nr][c0];
                bl2[nj][1] = *(const unsigned*)&Bl[nr][c0+8];
            }
            #pragma unroll
            for (int mi = 0; mi < 4; mi++)
                #pragma unroll
                for (int nj = 0; nj < 4; nj++) {
                    mma16816(acc[mi][nj], ah[mi], bh2[nj]);
                    mma16816(acc[mi][nj], ah[mi], bl2[nj]);
                    mma16816(acc[mi][nj], al[mi], bh2[nj]);
                }
        }

        if (t + 1 < NT) { cvt16(fa, pah, pal); cvt16(fb, pbh, pbl); }
    }

    // epilogue: scatter into window layout
    int nbase = n0 + wn*32;               // multiple of 32
    int which = nbase / INNER;
    int hh    = (nbase % INNER) >> 5;
    float* gp = (which == 0) ? g_q : (which == 1) ? g_k : g_v;

    #pragma unroll
    for (int mi = 0; mi < 4; mi++) {
        #pragma unroll
        for (int half = 0; half < 2; half++) {
            int R   = m0 + wm*64 + mi*16 + g + half*8;
            int b2_ = R >> 12, Hh = (R >> 6) & 63, Ww = R & 63;
            int wdw = (Hh >> 3)*8 + (Ww >> 3);
            int ii  = (Hh & 7)*8 + (Ww & 7);
            size_t rowbase = ((((size_t)b2_*HEADS + hh)*NWIN + wdw)*M2 + ii)*HD;
            #pragma unroll
            for (int nj = 0; nj < 4; nj++) {
                int d = nj*8 + 2*tg;
                *(float2*)(gp + rowbase + d) =
                    make_float2(acc[mi][nj][half*2+0], acc[mi][nj][half*2+1]);
            }
        }
    }
}

// ============================================================
// Output projection GEMM: bf16x3 mma. M=131072, N=384, K=384.
// roll(+4,+4) folded into A reads; + bias epilogue.
// ============================================================
__global__ __launch_bounds__(256) void out_gemm(
    const float* __restrict__ wout, const float* __restrict__ bout,
    float* __restrict__ y)
{
    __shared__ __align__(16) __nv_bfloat16 Ah[128][SMS];
    __shared__ __align__(16) __nv_bfloat16 Al[128][SMS];
    __shared__ __align__(16) __nv_bfloat16 Bh[128][SMS];
    __shared__ __align__(16) __nv_bfloat16 Bl[128][SMS];

    const int tid  = threadIdx.x;
    const int m0   = blockIdx.y * 128;
    const int n0   = blockIdx.x * 128;
    const int lane = tid & 31, warp = tid >> 5;
    const int wm = warp & 1, wn = warp >> 1;
    const int g  = lane >> 2, tg = lane & 3;

    const int rA = tid >> 1;
    const int cb = (tid & 1) * 16;
    int r  = m0 + rA;
    int bb = r >> 12, H = (r >> 6) & 63, W = r & 63;
    const float* arow = g_ao + (((size_t)bb*GRID + ((H+60)&63))*GRID + ((W+60)&63))*(size_t)INNER + cb;
    const float* brow = wout + (size_t)(n0 + rA)*INNER + cb;

    float fa[16], fb[16];
    uint4 pah[2], pal[2], pbh[2], pbl[2];

    #pragma unroll
    for (int u = 0; u < 4; u++) {
        float4 va = *(const float4*)(arow + u*4);
        float4 vb = *(const float4*)(brow + u*4);
        fa[u*4+0]=va.x; fa[u*4+1]=va.y; fa[u*4+2]=va.z; fa[u*4+3]=va.w;
        fb[u*4+0]=vb.x; fb[u*4+1]=vb.y; fb[u*4+2]=vb.z; fb[u*4+3]=vb.w;
    }
    cvt16(fa, pah, pal);
    cvt16(fb, pbh, pbl);

    float acc[4][4][4];
    #pragma unroll
    for (int i = 0; i < 4; i++)
        #pragma unroll
        for (int j = 0; j < 4; j++)
            #pragma unroll
            for (int u = 0; u < 4; u++) acc[i][j][u] = 0.f;

    const int NT = INNER / 32;  // 12
    for (int t = 0; t < NT; t++) {
        __syncthreads();
        *(uint4*)&Ah[rA][cb]   = pah[0];  *(uint4*)&Ah[rA][cb+8] = pah[1];
        *(uint4*)&Al[rA][cb]   = pal[0];  *(uint4*)&Al[rA][cb+8] = pal[1];
        *(uint4*)&Bh[rA][cb]   = pbh[0];  *(uint4*)&Bh[rA][cb+8] = pbh[1];
        *(uint4*)&Bl[rA][cb]   = pbl[0];  *(uint4*)&Bl[rA][cb+8] = pbl[1];
        __syncthreads();

        if (t + 1 < NT) {
            const float* an = arow + (t+1)*32;
            const float* bn = brow + (t+1)*32;
            #pragma unroll
            for (int u = 0; u < 4; u++) {
                float4 va = *(const float4*)(an + u*4);
                float4 vb = *(const float4*)(bn + u*4);
                fa[u*4+0]=va.x; fa[u*4+1]=va.y; fa[u*4+2]=va.z; fa[u*4+3]=va.w;
                fb[u*4+0]=vb.x; fb[u*4+1]=vb.y; fb[u*4+2]=vb.z; fb[u*4+3]=vb.w;
            }
        }

        #pragma unroll
        for (int ks = 0; ks < 2; ks++) {
            unsigned ah[4][4], al[4][4], bh2[4][2], bl2[4][2];
            const int c0 = ks*16 + 2*tg;
            #pragma unroll
            for (int mi = 0; mi < 4; mi++) {
                int r0 = wm*64 + mi*16 + g;
                ah[mi][0] = *(const unsigned*)&Ah[r0  ][c0];
                ah[mi][1] = *(const unsigned*)&Ah[r0+8][c0];
                ah[mi][2] = *(const unsigned*)&Ah[r0  ][c0+8];
                ah[mi][3] = *(const unsigned*)&Ah[r0+8][c0+8];
                al[mi][0] = *(const unsigned*)&Al[r0  ][c0];
                al[mi][1] = *(const unsigned*)&Al[r0+8][c0];
                al[mi][2] = *(const unsigned*)&Al[r0  ][c0+8];
                al[mi][3] = *(const unsigned*)&Al[r0+8][c0+8];
            }
            #pragma unroll
            for (int nj = 0; nj < 4; nj++) {
                int nr = wn*32 + nj*8 + g;
                bh2[nj][0] = *(const unsigned*)&Bh[nr][c0];
                bh2[nj][1] = *(const unsigned*)&Bh[nr][c0+8];
                bl2[nj][0] = *(const unsigned*)&Bl[nr][c0];
                bl2[nj][1] = *(const unsigned*)&Bl[nr][c0+8];
            }
            #pragma unroll
            for (int mi = 0; mi < 4; mi++)
                #pragma unroll
                for (int nj = 0; nj < 4; nj++) {
                    mma16816(acc[mi][nj], ah[mi], bh2[nj]);
                    mma16816(acc[mi][nj], ah[mi], bl2[nj]);
                    mma16816(acc[mi][nj], al[mi], bh2[nj]);
                }
        }

        if (t + 1 < NT) { cvt16(fa, pah, pal); cvt16(fb, pbh, pbl); }
    }

    // epilogue: + bias, store to y
    float2 bv[4];
    #pragma unroll
    for (int nj = 0; nj < 4; nj++)
        bv[nj] = *(const float2*)&bout[n0 + wn*32 + nj*8 + 2*tg];

    #pragma unroll
    for (int mi = 0; mi < 4; mi++) {
        #pragma unroll
        for (int half = 0; half < 2; half++) {
            size_t R = (size_t)(m0 + wm*64 + mi*16 + g + half*8);
            #pragma unroll
            for (int nj = 0; nj < 4; nj++) {
                int C = n0 + wn*32 + nj*8 + 2*tg;
                *(float2*)(y + R*DIM + C) =
                    make_float2(acc[mi][nj][half*2+0] + bv[nj].x,
                                acc[mi][nj][half*2+1] + bv[nj].y);
            }
        }
    }
}

// ============================================================
// Fused per-window attention: register-tiled dots/AV.
// ============================================================
__global__ __launch_bounds__(256) void attn_kernel(
    const float* __restrict__ tau, float* __restrict__ attn_out)
{
    __shared__ float sqt[HD][M2+4];                 // q transposed [d][i]
    __shared__ float skt[HD][M2+4];                 // k transposed [d][j]
    __shared__ __align__(16) float sv[M2][HD];
    __shared__ float sd[M2][M2+4];

    int blk = blockIdx.x;
    int w   = blk & 63;
    int bh  = blk >> 6;
    int h   = bh % HEADS;
    int tid = threadIdx.x;

    size_t base = (size_t)blk * (M2*HD);

    // load q,k transposed; v natural
    {
        int i  = tid >> 2;
        int d0 = (tid & 3) * 8;
        float4 q0 = *(const float4*)(g_q + base + (size_t)i*HD + d0);
        float4 q1 = *(const float4*)(g_q + base + (size_t)i*HD + d0 + 4);
        sqt[d0+0][i]=q0.x; sqt[d0+1][i]=q0.y; sqt[d0+2][i]=q0.z; sqt[d0+3][i]=q0.w;
        sqt[d0+4][i]=q1.x; sqt[d0+5][i]=q1.y; sqt[d0+6][i]=q1.z; sqt[d0+7][i]=q1.w;
        float4 k0 = *(const float4*)(g_k + base + (size_t)i*HD + d0);
        float4 k1 = *(const float4*)(g_k + base + (size_t)i*HD + d0 + 4);
        skt[d0+0][i]=k0.x; skt[d0+1][i]=k0.y; skt[d0+2][i]=k0.z; skt[d0+3][i]=k0.w;
        skt[d0+4][i]=k1.x; skt[d0+5][i]=k1.y; skt[d0+6][i]=k1.z; skt[d0+7][i]=k1.w;
        int idx = tid * 8;
        *(float4*)(&sv[0][0] + idx)     = *(const float4*)(g_v + base + idx);
        *(float4*)(&sv[0][0] + idx + 4) = *(const float4*)(g_v + base + idx + 4);
    }
    __syncthreads();

    // L2 normalize columns of sqt (threads 0..63) and skt (64..127)
    if (tid < 128) {
        int i = tid & 63;
        float s = 0.f;
        if (tid < 64) {
            #pragma unroll
            for (int d = 0; d < HD; d++) s = fmaf(sqt[d][i], sqt[d][i], s);
            float inv = 1.f / fmaxf(sqrtf(s), 1e-12f);
            #pragma unroll
            for (int d = 0; d < HD; d++) sqt[d][i] *= inv;
        } else {
            #pragma unroll
            for (int d = 0; d < HD; d++) s = fmaf(skt[d][i], skt[d][i], s);
            float inv = 1.f / fmaxf(sqrtf(s), 1e-12f);
            #pragma unroll
            for (int d = 0; d < HD; d++) skt[d][i] *= inv;
        }
    }
    __syncthreads();

    float inv_tau = 1.f / fmaxf(tau[h], 0.01f);
    int wh = w >> 3, ww = w & 7;
    bool mUL = (wh == 7), mLR = (ww == 7);

    // dots: 4x4 register tile per thread
    {
        int i0 = (tid >> 4) * 4;
        int j0 = (tid & 15) * 4;
        float acc[4][4];
        #pragma unroll
        for (int a = 0; a < 4; a++)
            #pragma unroll
            for (int b = 0; b < 4; b++) acc[a][b] = 0.f;

        #pragma unroll 4
        for (int k = 0; k < HD; k++) {
            float4 qv = *(const float4*)&sqt[k][i0];
            float4 kv = *(const float4*)&skt[k][j0];
            float qa[4] = {qv.x, qv.y, qv.z, qv.w};
            float ka[4] = {kv.x, kv.y, kv.z, kv.w};
            #pragma unroll
            for (int a = 0; a < 4; a++)
                #pragma unroll
                for (int b = 0; b < 4; b++)
                    acc[a][b] = fmaf(qa[a], ka[b], acc[a][b]);
        }

        #pragma unroll
        for (int a = 0; a < 4; a++) {
            int i = i0 + a;
            bool iu = (i >= 32);
            bool il = ((i & 7) >= 4);
            const float* biasrow = g_bias + ((size_t)h*M2 + i)*M2;
            #pragma unroll
            for (int b = 0; b < 4; b++) {
                int j = j0 + b;
                float val = fmaf(acc[a][b], inv_tau, biasrow[j]);
                if (mUL && (iu != (j >= 32)))      val = -1e30f;
                if (mLR && (il != ((j & 7) >= 4))) val = -1e30f;
                sd[i][j] = val;
            }
        }
    }
    __syncthreads();

    // softmax: 8 warps x 8 rows; 2 cols per lane; write attn
    {
        int lane = tid & 31, wp = tid >> 5;
        for (int rr = 0; rr < 8; rr++) {
            int row = wp*8 + rr;
            float v0 = sd[row][lane], v1 = sd[row][lane+32];
            float mx = fmaxf(v0, v1);
            #pragma unroll
            for (int o = 16; o > 0; o >>= 1)
                mx = fmaxf(mx, __shfl_xor_sync(0xffffffffu, mx, o));
            float e0 = __expf(v0 - mx), e1 = __expf(v1 - mx);
            float sm = e0 + e1;
            #pragma unroll
            for (int o = 16; o > 0; o >>= 1)
                sm += __shfl_xor_sync(0xffffffffu, sm, o);
            float inv = 1.f / sm;
            e0 *= inv; e1 *= inv;
            sd[row][lane]    = e0;
            sd[row][lane+32] = e1;
            if (attn_out) {
                size_t ab = ((size_t)blk*M2 + row)*M2;
                attn_out[ab + lane]      = e0;
                attn_out[ab + lane + 32] = e1;
            }
        }
    }
    __syncthreads();

    // AV: 4 rows x 2 d per thread
    {
        int i0 = (tid >> 4) * 4;
        int d0 = (tid & 15) * 2;
        float acc[4][2];
        #pragma unroll
        for (int a = 0; a < 4; a++) { acc[a][0] = 0.f; acc[a][1] = 0.f; }

        #pragma unroll 4
        for (int j = 0; j < M2; j++) {
            float2 vv = *(const float2*)&sv[j][d0];
            #pragma unroll
            for (int a = 0; a < 4; a++) {
                float at = sd[i0 + a][j];
                acc[a][0] = fmaf(at, vv.x, acc[a][0]);
                acc[a][1] = fmaf(at, vv.y, acc[a][1]);
            }
        }

        int b = bh / HEADS;
        #pragma unroll
        for (int a = 0; a < 4; a++) {
            int i  = i0 + a;
            int Hh = wh*8 + (i >> 3);
            int Ww = ww*8 + (i & 7);
            float* op = g_ao + (((size_t)b*GRID + Hh)*GRID + Ww)*INNER + h*HD + d0;
            *(float2*)op = make_float2(acc[a][0], acc[a][1]);
        }
    }
}

// ============================================================
extern "C" void kernel_launch(void* const* d_in, const int* in_sizes, int n_in,
                              void* d_out, int out_size)
{
    const float* x    = (const float*)d_in[0];
    const float* wqkv = (const float*)d_in[1];
    const float* w1   = (const float*)d_in[2];
    const float* b1   = (const float*)d_in[3];
    const float* w2   = (const float*)d_in[4];
    const float* b2   = (const float*)d_in[5];
    const float* tau  = (const float*)d_in[6];
    const float* wout = (const float*)d_in[7];
    const float* bout = (const float*)d_in[8];

    float* out = (float*)d_out;
    const long long OUT_E  = (long long)ROWS * DIM;
    const long long ATTN_E = (long long)BATCH*HEADS*NWIN*M2*M2;
    float* attn = ((long long)out_size >= OUT_E + ATTN_E) ? (out + OUT_E) : nullptr;

    cpb_kernel<<<16, 256>>>(w1, b1, w2, b2);
    qkv_gemm<<<dim3(QKV_N/128, ROWS/128), 256>>>(x, wqkv);
    attn_kernel<<<BATCH*HEADS*NWIN, 256>>>(tau, attn);
    out_gemm<<<dim3(DIM/128, ROWS/128), 256>>>(wout, bout, out);
}